// round 1
// baseline (speedup 1.0000x reference)
#include <cuda_runtime.h>
#include <math.h>

#define SEQ     16384
#define IN_DIM  512
#define HID     1024
#define OUT_DIM 256

#define NB      128     // scan blocks (must be < 148 SMs for residency)
#define RPB     8       // hidden rows per block (NB*RPB == HID)
#define SCAN_T  256     // 8 warps, one per row

// ---- scratch (static __device__ per harness rules; no allocs anywhere) ----
__device__ float    g_xh[SEQ * HID];     // 64 MB  xh = input@Wxh.T + bias
__device__ float    g_outs[SEQ * HID];   // 64 MB  all hidden states
__device__ float    g_h[2][HID];         // double-buffered recurrent state
__device__ float    g_bias[HID];         // Wxh_b + Whh_b + bh
__device__ unsigned g_arrive;            // grid barrier counter

// ---------------------------------------------------------------- reset ----
__global__ void reset_kernel(const float* __restrict__ hidden,
                             const float* __restrict__ wxb,
                             const float* __restrict__ whb,
                             const float* __restrict__ bh) {
    int i = threadIdx.x;  // 1024 threads
    if (i == 0) g_arrive = 0u;
    g_h[0][i]  = hidden[i];
    g_bias[i]  = wxb[i] + whb[i] + bh[i];
}

// --------------------------------------------------- generic NT fp32 GEMM --
// C[m][n] = sum_k A[m][k] * B[n][k] + bias[n]
// BM=BN=64, BK=16, 256 threads, 4x4 per-thread tile.
__global__ void gemm_nt_bias(const float* __restrict__ A,
                             const float* __restrict__ B,
                             const float* __restrict__ bias,
                             float* __restrict__ C,
                             int M, int N, int K) {
    __shared__ float As[16][65];
    __shared__ float Bs[16][65];
    const int tid = threadIdx.x;
    const int bx = blockIdx.x;          // n tile
    const int by = blockIdx.y;          // m tile
    const int tm = (tid >> 4) << 2;     // 0..60
    const int tn = (tid & 15) << 2;     // 0..60
    const int lr = tid >> 2;            // 0..63  (load row)
    const int lk = (tid & 3) << 2;      // 0,4,8,12

    const float* Ap = A + (size_t)(by * 64 + lr) * K + lk;
    const float* Bp = B + (size_t)(bx * 64 + lr) * K + lk;

    float acc[4][4] = {};

    for (int k0 = 0; k0 < K; k0 += 16) {
        float4 av = *(const float4*)(Ap + k0);
        float4 bv = *(const float4*)(Bp + k0);
        As[lk + 0][lr] = av.x; As[lk + 1][lr] = av.y;
        As[lk + 2][lr] = av.z; As[lk + 3][lr] = av.w;
        Bs[lk + 0][lr] = bv.x; Bs[lk + 1][lr] = bv.y;
        Bs[lk + 2][lr] = bv.z; Bs[lk + 3][lr] = bv.w;
        __syncthreads();
#pragma unroll
        for (int k = 0; k < 16; k++) {
            float ra[4], rb[4];
#pragma unroll
            for (int i = 0; i < 4; i++) ra[i] = As[k][tm + i];
#pragma unroll
            for (int j = 0; j < 4; j++) rb[j] = Bs[k][tn + j];
#pragma unroll
            for (int i = 0; i < 4; i++)
#pragma unroll
                for (int j = 0; j < 4; j++)
                    acc[i][j] += ra[i] * rb[j];
        }
        __syncthreads();
    }

    float bb[4];
#pragma unroll
    for (int j = 0; j < 4; j++) bb[j] = bias[bx * 64 + tn + j];
#pragma unroll
    for (int i = 0; i < 4; i++) {
        int row = by * 64 + tm + i;
        float* cp = C + (size_t)row * N + bx * 64 + tn;
#pragma unroll
        for (int j = 0; j < 4; j++) cp[j] = acc[i][j] + bb[j];
    }
}

// ---------------------------------------------------------- persistent scan
// 128 blocks x 256 threads. Warp w of block b owns hidden row b*8+w, with
// Whh row held in 32 registers (lane l covers columns k*32+l). One global
// barrier per step; h double-buffered in global (L2-resident).
__global__ void __launch_bounds__(SCAN_T, 1)
scan_kernel(const float* __restrict__ Whh) {
    const int bid  = blockIdx.x;
    const int tid  = threadIdx.x;
    const int wid  = tid >> 5;
    const int lane = tid & 31;
    const int row  = bid * RPB + wid;

    // pin Whh row slice in registers
    float w[32];
#pragma unroll
    for (int k = 0; k < 32; k++)
        w[k] = Whh[(size_t)row * HID + k * 32 + lane];

    __shared__ float hs[HID];

    unsigned target = NB;
    float xh_next = g_xh[row];   // prefetch step 0 (uniform per warp)

    for (int t = 0; t < SEQ; t++) {
        const int p = t & 1;

        // stage h into shared (L2 path; bypass L1 for cross-SM coherence)
#pragma unroll
        for (int i = tid; i < HID; i += SCAN_T)
            hs[i] = __ldcg(&g_h[p][i]);
        __syncthreads();

        float xh_cur = xh_next;
        if (t + 1 < SEQ) xh_next = g_xh[(size_t)(t + 1) * HID + row];

        float a0 = 0.f, a1 = 0.f, a2 = 0.f, a3 = 0.f;
#pragma unroll
        for (int k = 0; k < 32; k += 4) {
            a0 += w[k + 0] * hs[(k + 0) * 32 + lane];
            a1 += w[k + 1] * hs[(k + 1) * 32 + lane];
            a2 += w[k + 2] * hs[(k + 2) * 32 + lane];
            a3 += w[k + 3] * hs[(k + 3) * 32 + lane];
        }
        float acc = (a0 + a1) + (a2 + a3);
#pragma unroll
        for (int o = 16; o > 0; o >>= 1)
            acc += __shfl_xor_sync(0xFFFFFFFFu, acc, o);

        if (lane == 0) {
            float hn = tanhf(xh_cur + acc);
            g_h[p ^ 1][row] = hn;
            g_outs[(size_t)t * HID + row] = hn;
        }
        __syncthreads();                       // all rows written

        if (tid == 0) {                        // grid barrier (release/acquire)
            __threadfence();
            atomicAdd(&g_arrive, 1u);
            volatile unsigned* va = &g_arrive;
            while (*va < target) { }
            __threadfence();
        }
        __syncthreads();
        target += NB;
    }
}

// ----------------------------------------------------------- row softmax ---
__global__ void softmax256(float* __restrict__ X) {
    const int r = blockIdx.x;
    const int tid = threadIdx.x;          // 256
    const int wid = tid >> 5, lane = tid & 31;
    __shared__ float red[8];

    float v = X[(size_t)r * OUT_DIM + tid];

    float m = v;
#pragma unroll
    for (int o = 16; o > 0; o >>= 1)
        m = fmaxf(m, __shfl_xor_sync(0xFFFFFFFFu, m, o));
    if (lane == 0) red[wid] = m;
    __syncthreads();
    if (tid == 0) {
        float mm = red[0];
#pragma unroll
        for (int i = 1; i < 8; i++) mm = fmaxf(mm, red[i]);
        red[0] = mm;
    }
    __syncthreads();
    const float bm = red[0];
    __syncthreads();

    float e = expf(v - bm);
    float s = e;
#pragma unroll
    for (int o = 16; o > 0; o >>= 1)
        s += __shfl_xor_sync(0xFFFFFFFFu, s, o);
    if (lane == 0) red[wid] = s;
    __syncthreads();
    if (tid == 0) {
        float ss = red[0];
#pragma unroll
        for (int i = 1; i < 8; i++) ss += red[i];
        red[0] = ss;
    }
    __syncthreads();
    X[(size_t)r * OUT_DIM + tid] = e / red[0];
}

// ------------------------------------------------------------------ launch -
extern "C" void kernel_launch(void* const* d_in, const int* in_sizes, int n_in,
                              void* d_out, int out_size) {
    const float* input  = (const float*)d_in[0];   // (SEQ, IN)
    const float* hidden = (const float*)d_in[1];   // (HID,)
    const float* Wxh_w  = (const float*)d_in[2];   // (HID, IN)
    const float* Wxh_b  = (const float*)d_in[3];   // (HID,)
    const float* Whh_w  = (const float*)d_in[4];   // (HID, HID)
    const float* Whh_b  = (const float*)d_in[5];   // (HID,)
    const float* bh     = (const float*)d_in[6];   // (HID,)
    const float* fc_w   = (const float*)d_in[7];   // (OUT, HID)
    const float* fc_b   = (const float*)d_in[8];   // (OUT,)
    float* out = (float*)d_out;                    // (SEQ, OUT)

    // resolve scratch symbol addresses (pure address queries, no allocation)
    float* xh_ptr   = nullptr;
    float* outs_ptr = nullptr;
    float* bias_ptr = nullptr;
    cudaGetSymbolAddress((void**)&xh_ptr,   g_xh);
    cudaGetSymbolAddress((void**)&outs_ptr, g_outs);
    cudaGetSymbolAddress((void**)&bias_ptr, g_bias);

    // 0) reset barrier counter, init h0, fold the three bias vectors
    reset_kernel<<<1, HID>>>(hidden, Wxh_b, Whh_b, bh);

    // 1) xh = input @ Wxh.T + bias        (M=SEQ, N=HID, K=IN)
    {
        dim3 grid(HID / 64, SEQ / 64);
        gemm_nt_bias<<<grid, 256>>>(input, Wxh_w, bias_ptr, xh_ptr,
                                    SEQ, HID, IN_DIM);
    }

    // 2) sequential recurrence (persistent kernel, grid barrier per step)
    scan_kernel<<<NB, SCAN_T>>>(Whh_w);

    // 3) logits = outs @ fc_w.T + fc_b    (M=SEQ, N=OUT, K=HID) -> d_out
    {
        dim3 grid(OUT_DIM / 64, SEQ / 64);
        gemm_nt_bias<<<grid, 256>>>(outs_ptr, fc_w, fc_b, out,
                                    SEQ, OUT_DIM, HID);
    }

    // 4) softmax rows in place on d_out
    softmax256<<<SEQ, OUT_DIM>>>(out);
}

// round 2
// speedup vs baseline: 1.0108x; 1.0108x over previous
#include <cuda_runtime.h>
#include <math.h>

#define SEQ     16384
#define IN_DIM  512
#define HID     1024
#define OUT_DIM 256

#define NB      128     // scan blocks (must be < 148 SMs for residency)
#define RPB     8       // hidden rows per block (NB*RPB == HID)
#define SCAN_T  256     // 8 warps, one per row

// ---- scratch (static __device__ per harness rules; no allocs anywhere) ----
__device__ float    g_xh[SEQ * HID];     // 64 MB  xh = input@Wxh.T + bias
__device__ float    g_outs[SEQ * HID];   // 64 MB  all hidden states
__device__ float    g_h[2][HID];         // double-buffered recurrent state
__device__ float    g_bias[HID];         // Wxh_b + Whh_b + bh
__device__ unsigned g_arrive;            // grid barrier counter

// ---------------------------------------------------------------- reset ----
__global__ void reset_kernel(const float* __restrict__ hidden,
                             const float* __restrict__ wxb,
                             const float* __restrict__ whb,
                             const float* __restrict__ bh) {
    int i = threadIdx.x;  // 1024 threads
    if (i == 0) g_arrive = 0u;
    g_h[0][i]  = hidden[i];
    g_bias[i]  = wxb[i] + whb[i] + bh[i];
}

// --------------------------------------------------- generic NT fp32 GEMM --
// C[m][n] = sum_k A[m][k] * B[n][k] + bias[n]
// BM=BN=64, BK=16, 256 threads, 4x4 per-thread tile.
__global__ void gemm_nt_bias(const float* __restrict__ A,
                             const float* __restrict__ B,
                             const float* __restrict__ bias,
                             float* __restrict__ C,
                             int M, int N, int K) {
    __shared__ float As[16][65];
    __shared__ float Bs[16][65];
    const int tid = threadIdx.x;
    const int bx = blockIdx.x;          // n tile
    const int by = blockIdx.y;          // m tile
    const int tm = (tid >> 4) << 2;     // 0..60
    const int tn = (tid & 15) << 2;     // 0..60
    const int lr = tid >> 2;            // 0..63  (load row)
    const int lk = (tid & 3) << 2;      // 0,4,8,12

    const float* Ap = A + (size_t)(by * 64 + lr) * K + lk;
    const float* Bp = B + (size_t)(bx * 64 + lr) * K + lk;

    float acc[4][4] = {};

    for (int k0 = 0; k0 < K; k0 += 16) {
        float4 av = *(const float4*)(Ap + k0);
        float4 bv = *(const float4*)(Bp + k0);
        As[lk + 0][lr] = av.x; As[lk + 1][lr] = av.y;
        As[lk + 2][lr] = av.z; As[lk + 3][lr] = av.w;
        Bs[lk + 0][lr] = bv.x; Bs[lk + 1][lr] = bv.y;
        Bs[lk + 2][lr] = bv.z; Bs[lk + 3][lr] = bv.w;
        __syncthreads();
#pragma unroll
        for (int k = 0; k < 16; k++) {
            float ra[4], rb[4];
#pragma unroll
            for (int i = 0; i < 4; i++) ra[i] = As[k][tm + i];
#pragma unroll
            for (int j = 0; j < 4; j++) rb[j] = Bs[k][tn + j];
#pragma unroll
            for (int i = 0; i < 4; i++)
#pragma unroll
                for (int j = 0; j < 4; j++)
                    acc[i][j] += ra[i] * rb[j];
        }
        __syncthreads();
    }

    float bb[4];
#pragma unroll
    for (int j = 0; j < 4; j++) bb[j] = bias[bx * 64 + tn + j];
#pragma unroll
    for (int i = 0; i < 4; i++) {
        int row = by * 64 + tm + i;
        float* cp = C + (size_t)row * N + bx * 64 + tn;
#pragma unroll
        for (int j = 0; j < 4; j++) cp[j] = acc[i][j] + bb[j];
    }
}

// ---------------------------------------------------------- persistent scan
// 128 blocks x 256 threads. Warp w of block b owns hidden row b*8+w, with
// Whh row held in 32 registers (lane l covers columns k*32+l). One global
// barrier per step; h double-buffered in global (L2-resident).
__global__ void __launch_bounds__(SCAN_T, 1)
scan_kernel(const float* __restrict__ Whh) {
    const int bid  = blockIdx.x;
    const int tid  = threadIdx.x;
    const int wid  = tid >> 5;
    const int lane = tid & 31;
    const int row  = bid * RPB + wid;

    // pin Whh row slice in registers
    float w[32];
#pragma unroll
    for (int k = 0; k < 32; k++)
        w[k] = Whh[(size_t)row * HID + k * 32 + lane];

    __shared__ float hs[HID];

    unsigned target = NB;
    float xh_next = g_xh[row];   // prefetch step 0 (uniform per warp)

    for (int t = 0; t < SEQ; t++) {
        const int p = t & 1;

        // stage h into shared (L2 path; bypass L1 for cross-SM coherence)
#pragma unroll
        for (int i = tid; i < HID; i += SCAN_T)
            hs[i] = __ldcg(&g_h[p][i]);
        __syncthreads();

        float xh_cur = xh_next;
        if (t + 1 < SEQ) xh_next = g_xh[(size_t)(t + 1) * HID + row];

        float a0 = 0.f, a1 = 0.f, a2 = 0.f, a3 = 0.f;
#pragma unroll
        for (int k = 0; k < 32; k += 4) {
            a0 += w[k + 0] * hs[(k + 0) * 32 + lane];
            a1 += w[k + 1] * hs[(k + 1) * 32 + lane];
            a2 += w[k + 2] * hs[(k + 2) * 32 + lane];
            a3 += w[k + 3] * hs[(k + 3) * 32 + lane];
        }
        float acc = (a0 + a1) + (a2 + a3);
#pragma unroll
        for (int o = 16; o > 0; o >>= 1)
            acc += __shfl_xor_sync(0xFFFFFFFFu, acc, o);

        if (lane == 0) {
            float hn = tanhf(xh_cur + acc);
            g_h[p ^ 1][row] = hn;
            g_outs[(size_t)t * HID + row] = hn;
        }
        __syncthreads();                       // all rows written

        if (tid == 0) {                        // grid barrier (release/acquire)
            __threadfence();
            atomicAdd(&g_arrive, 1u);
            volatile unsigned* va = &g_arrive;
            while (*va < target) { }
            __threadfence();
        }
        __syncthreads();
        target += NB;
    }
}

// ----------------------------------------------------------- row softmax ---
__global__ void softmax256(float* __restrict__ X) {
    const int r = blockIdx.x;
    const int tid = threadIdx.x;          // 256
    const int wid = tid >> 5, lane = tid & 31;
    __shared__ float red[8];

    float v = X[(size_t)r * OUT_DIM + tid];

    float m = v;
#pragma unroll
    for (int o = 16; o > 0; o >>= 1)
        m = fmaxf(m, __shfl_xor_sync(0xFFFFFFFFu, m, o));
    if (lane == 0) red[wid] = m;
    __syncthreads();
    if (tid == 0) {
        float mm = red[0];
#pragma unroll
        for (int i = 1; i < 8; i++) mm = fmaxf(mm, red[i]);
        red[0] = mm;
    }
    __syncthreads();
    const float bm = red[0];
    __syncthreads();

    float e = expf(v - bm);
    float s = e;
#pragma unroll
    for (int o = 16; o > 0; o >>= 1)
        s += __shfl_xor_sync(0xFFFFFFFFu, s, o);
    if (lane == 0) red[wid] = s;
    __syncthreads();
    if (tid == 0) {
        float ss = red[0];
#pragma unroll
        for (int i = 1; i < 8; i++) ss += red[i];
        red[0] = ss;
    }
    __syncthreads();
    X[(size_t)r * OUT_DIM + tid] = e / red[0];
}

// ------------------------------------------------------------------ launch -
extern "C" void kernel_launch(void* const* d_in, const int* in_sizes, int n_in,
                              void* d_out, int out_size) {
    const float* input  = (const float*)d_in[0];   // (SEQ, IN)
    const float* hidden = (const float*)d_in[1];   // (HID,)
    const float* Wxh_w  = (const float*)d_in[2];   // (HID, IN)
    const float* Wxh_b  = (const float*)d_in[3];   // (HID,)
    const float* Whh_w  = (const float*)d_in[4];   // (HID, HID)
    const float* Whh_b  = (const float*)d_in[5];   // (HID,)
    const float* bh     = (const float*)d_in[6];   // (HID,)
    const float* fc_w   = (const float*)d_in[7];   // (OUT, HID)
    const float* fc_b   = (const float*)d_in[8];   // (OUT,)
    float* out = (float*)d_out;                    // (SEQ, OUT)

    // resolve scratch symbol addresses (pure address queries, no allocation)
    float* xh_ptr   = nullptr;
    float* outs_ptr = nullptr;
    float* bias_ptr = nullptr;
    cudaGetSymbolAddress((void**)&xh_ptr,   g_xh);
    cudaGetSymbolAddress((void**)&outs_ptr, g_outs);
    cudaGetSymbolAddress((void**)&bias_ptr, g_bias);

    // 0) reset barrier counter, init h0, fold the three bias vectors
    reset_kernel<<<1, HID>>>(hidden, Wxh_b, Whh_b, bh);

    // 1) xh = input @ Wxh.T + bias        (M=SEQ, N=HID, K=IN)
    {
        dim3 grid(HID / 64, SEQ / 64);
        gemm_nt_bias<<<grid, 256>>>(input, Wxh_w, bias_ptr, xh_ptr,
                                    SEQ, HID, IN_DIM);
    }

    // 2) sequential recurrence (persistent kernel, grid barrier per step)
    scan_kernel<<<NB, SCAN_T>>>(Whh_w);

    // 3) logits = outs @ fc_w.T + fc_b    (M=SEQ, N=OUT, K=HID) -> d_out
    {
        dim3 grid(OUT_DIM / 64, SEQ / 64);
        gemm_nt_bias<<<grid, 256>>>(outs_ptr, fc_w, fc_b, out,
                                    SEQ, OUT_DIM, HID);
    }

    // 4) softmax rows in place on d_out
    softmax256<<<SEQ, OUT_DIM>>>(out);
}